// round 1
// baseline (speedup 1.0000x reference)
#include <cuda_runtime.h>
#include <cstdint>

namespace {

constexpr int CI = 64;   // C_L_IN
constexpr int CO = 64;   // C_L_OUT
constexpr int CJ = 16;   // C_J

using ull = unsigned long long;

// ---- sm_103a packed fp32x2 helpers (double-rate fp32 FMA, PTX-only path) ----
__device__ __forceinline__ ull fma2(ull a, ull b, ull c) {
    ull d;
    asm("fma.rn.f32x2 %0, %1, %2, %3;" : "=l"(d) : "l"(a), "l"(b), "l"(c));
    return d;
}
__device__ __forceinline__ ull splat2(float x) {
    ull r;
    asm("mov.b64 %0, {%1, %1};" : "=l"(r) : "f"(x));
    return r;
}
__device__ __forceinline__ ull pack2(float lo, float hi) {
    ull r;
    asm("mov.b64 %0, {%1, %2};" : "=l"(r) : "f"(lo), "f"(hi));
    return r;
}
__device__ __forceinline__ void unpack2(ull v, float& lo, float& hi) {
    asm("mov.b64 {%0, %1}, %2;" : "=f"(lo), "=f"(hi) : "l"(v));
}

// ---- cp.async double-buffer helpers ----
__device__ __forceinline__ void cpa16(uint32_t s, const float* g) {
    asm volatile("cp.async.cg.shared.global [%0], [%1], 16;" :: "r"(s), "l"(g));
}
__device__ __forceinline__ void cp_commit() { asm volatile("cp.async.commit_group;"); }
template <int N>
__device__ __forceinline__ void cp_wait() { asm volatile("cp.async.wait_group %0;" :: "n"(N)); }

// smem layout per buffer (floats):
//   [0..16)    W_bias [j,i,:,:]      (16)
//   [16..272)  W_cos  [j,i,:,:,:]    (256, layout c*16 + p*4 + q)
//   [272..528) W_sin                 (256)
//   [528..544) Wb_bias               (16)
//   [544..800) Wb_cos                (256)
//   [800..1056)Wb_sin                (256)
constexpr int SM_BIAS1 = 0, SM_COS1 = 16, SM_SIN1 = 272;
constexpr int SM_BIAS2 = 528, SM_COS2 = 544, SM_SIN2 = 800;
constexpr int SMEM_FLOATS = 1056;

}  // namespace

// One CTA = (j, block of 128 batch indices). One thread = one b for this j.
// Per i: build U[b,j,i] and Ub[b,j,i] (4x4 each) in registers from smem weight
// slice weighted by per-thread cos/sin splats, then accumulate
//   out[b,j] += F[b,i] @ U[b,j,i] + Ub[b,j,i] @ F[b,i].
__global__ void __launch_bounds__(128) nro_kernel(
    const float* __restrict__ F,     // (B, CI, 4, 4)
    const float* __restrict__ theta, // (B, CJ)
    const float* __restrict__ Wb,    // (CO, CI, 4, 4)
    const float* __restrict__ Wc,    // (CO, CI, CJ, 4, 4)
    const float* __restrict__ Ws,    // (CO, CI, CJ, 4, 4)
    const float* __restrict__ Wbb,   // (CO, CI, 4, 4)
    const float* __restrict__ Wbc,   // (CO, CI, CJ, 4, 4)
    const float* __restrict__ Wbs,   // (CO, CI, CJ, 4, 4)
    float* __restrict__ out)         // (B, CO, 4, 4)
{
    __shared__ __align__(16) float sm[2][SMEM_FLOATS];

    const int tid = threadIdx.x;
    const int j   = blockIdx.y;
    const int b   = blockIdx.x * 128 + tid;

    // Per-thread trig splats: v = [cos(theta_c)] , [sin(theta_c)]
    ull vc[CJ], vs[CJ];
#pragma unroll
    for (int c = 0; c < CJ; c++) {
        float sn, cs;
        sincosf(theta[b * CJ + c], &sn, &cs);
        vc[c] = splat2(cs);
        vs[c] = splat2(sn);
    }

    // Accumulators: a01[p] = {out[p][0], out[p][1]}, a23[p] = {out[p][2], out[p][3]}
    ull a01[4], a23[4];
#pragma unroll
    for (int p = 0; p < 4; p++) { a01[p] = 0ull; a23[p] = 0ull; }

    auto preload = [&](int buf, int i) {
        float* s = sm[buf];
        uint32_t sa = (uint32_t)__cvta_generic_to_shared(s);
        const int o256 = (j * CI + i) * 256;
        const int o16  = (j * CI + i) * 16;
        // 4 segments x 64 float4 = 256 float4 over 128 threads (2 each)
#pragma unroll
        for (int x = tid; x < 256; x += 128) {
            const int seg = x >> 6;
            const int w   = (x & 63) << 2;  // float offset within segment
            const float* g = (seg == 0) ? (Wc  + o256 + w)
                           : (seg == 1) ? (Ws  + o256 + w)
                           : (seg == 2) ? (Wbc + o256 + w)
                                        : (Wbs + o256 + w);
            const int so = (seg == 0) ? SM_COS1 : (seg == 1) ? SM_SIN1
                         : (seg == 2) ? SM_COS2 : SM_SIN2;
            cpa16(sa + (uint32_t)(so + w) * 4u, g);
        }
        if (tid < 8) {
            const float* g = ((tid < 4) ? Wb : Wbb) + o16 + (tid & 3) * 4;
            const int so   = ((tid < 4) ? SM_BIAS1 : SM_BIAS2) + (tid & 3) * 4;
            cpa16(sa + (uint32_t)so * 4u, g);
        }
    };

    preload(0, 0);
    cp_commit();

    for (int i = 0; i < CI; i++) {
        const int cur = i & 1;
        if (i + 1 < CI) {
            preload(cur ^ 1, i + 1);
            cp_commit();
            cp_wait<1>();   // current buffer's group has landed
        } else {
            cp_wait<0>();
        }
        __syncthreads();

        // F[b,i,:,:] — 16 contiguous floats
        const float4* Fp = (const float4*)(F + (b * CI + i) * 16);
        const float4 fA = Fp[0], fB = Fp[1], fC = Fp[2], fD = Fp[3];
        const float fr[4][4] = {
            {fA.x, fA.y, fA.z, fA.w}, {fB.x, fB.y, fB.z, fB.w},
            {fC.x, fC.y, fC.z, fC.w}, {fD.x, fD.y, fD.z, fD.w}};

        const float* s = sm[cur];
        const ulonglong2* b1 = (const ulonglong2*)(s + SM_BIAS1);
        const ulonglong2* c1 = (const ulonglong2*)(s + SM_COS1);
        const ulonglong2* s1 = (const ulonglong2*)(s + SM_SIN1);
        const ulonglong2* b2 = (const ulonglong2*)(s + SM_BIAS2);
        const ulonglong2* c2 = (const ulonglong2*)(s + SM_COS2);
        const ulonglong2* s2 = (const ulonglong2*)(s + SM_SIN2);

        // Build U (u01/u23, row index = U's dim-3) and Ub (t01/t23, row index = p)
        ull u01[4], u23[4], t01[4], t23[4];
#pragma unroll
        for (int r = 0; r < 4; r++) {
            ulonglong2 x = b1[r]; u01[r] = x.x; u23[r] = x.y;
            ulonglong2 y = b2[r]; t01[r] = y.x; t23[r] = y.y;
        }
#pragma unroll
        for (int c = 0; c < CJ; c++) {
#pragma unroll
            for (int r = 0; r < 4; r++) {
                ulonglong2 w;
                w = c1[c * 4 + r];
                u01[r] = fma2(w.x, vc[c], u01[r]);
                u23[r] = fma2(w.y, vc[c], u23[r]);
                w = s1[c * 4 + r];
                u01[r] = fma2(w.x, vs[c], u01[r]);
                u23[r] = fma2(w.y, vs[c], u23[r]);
                w = c2[c * 4 + r];
                t01[r] = fma2(w.x, vc[c], t01[r]);
                t23[r] = fma2(w.y, vc[c], t23[r]);
                w = s2[c * 4 + r];
                t01[r] = fma2(w.x, vs[c], t01[r]);
                t23[r] = fma2(w.y, vs[c], t23[r]);
            }
        }

        // term1: out[p][r] += sum_q F[p][q] * U[q][r]
#pragma unroll
        for (int p = 0; p < 4; p++) {
#pragma unroll
            for (int q = 0; q < 4; q++) {
                ull fs = splat2(fr[p][q]);
                a01[p] = fma2(fs, u01[q], a01[p]);
                a23[p] = fma2(fs, u23[q], a23[p]);
            }
        }

        // term2: out[p][r] += sum_q Ub[p][q] * F[q][r]
        ull f01[4], f23[4];
#pragma unroll
        for (int q = 0; q < 4; q++) {
            f01[q] = pack2(fr[q][0], fr[q][1]);
            f23[q] = pack2(fr[q][2], fr[q][3]);
        }
#pragma unroll
        for (int p = 0; p < 4; p++) {
            float g0, g1, g2, g3;
            unpack2(t01[p], g0, g1);
            unpack2(t23[p], g2, g3);
            const float gg[4] = {g0, g1, g2, g3};
#pragma unroll
            for (int q = 0; q < 4; q++) {
                ull gs = splat2(gg[q]);
                a01[p] = fma2(gs, f01[q], a01[p]);
                a23[p] = fma2(gs, f23[q], a23[p]);
            }
        }

        __syncthreads();  // protect 'cur' buffer before next iter's preload overwrites it
    }

    // out[b,j,p,r]
    float4* op = (float4*)(out + (b * CO + j) * 16);
#pragma unroll
    for (int p = 0; p < 4; p++) {
        float4 o;
        unpack2(a01[p], o.x, o.y);
        unpack2(a23[p], o.z, o.w);
        op[p] = o;
    }
}

extern "C" void kernel_launch(void* const* d_in, const int* in_sizes, int n_in,
                              void* d_out, int out_size) {
    (void)in_sizes; (void)n_in; (void)out_size;
    const float* F   = (const float*)d_in[0];
    const float* th  = (const float*)d_in[1];
    const float* Wb  = (const float*)d_in[2];
    const float* Wc  = (const float*)d_in[3];
    const float* Ws  = (const float*)d_in[4];
    const float* Wbb = (const float*)d_in[5];
    const float* Wbc = (const float*)d_in[6];
    const float* Wbs = (const float*)d_in[7];

    dim3 grid(4, 64);  // (batch blocks of 128, j)
    nro_kernel<<<grid, 128>>>(F, th, Wb, Wc, Ws, Wbb, Wbc, Wbs, (float*)d_out);
}

// round 2
// speedup vs baseline: 1.3472x; 1.3472x over previous
#include <cuda_runtime.h>
#include <cstdint>

namespace {

constexpr int CI = 64;   // C_L_IN
constexpr int CO = 64;   // C_L_OUT
constexpr int CJ = 16;   // C_J
constexpr int B  = 512;
constexpr int NB = 2;    // batches per thread
constexpr int NSEG = 4;  // split-K segments over i
constexpr int ISEG = CI / NSEG;  // 16
constexpr int OUT_ELEMS = B * CO * 16;  // 524288

using ull = unsigned long long;

// ---- sm_103a packed fp32x2 helpers (double-rate fp32 FMA, PTX-only path) ----
__device__ __forceinline__ ull fma2(ull a, ull b, ull c) {
    ull d;
    asm("fma.rn.f32x2 %0, %1, %2, %3;" : "=l"(d) : "l"(a), "l"(b), "l"(c));
    return d;
}
__device__ __forceinline__ ull splat2(float x) {
    ull r;
    asm("mov.b64 %0, {%1, %1};" : "=l"(r) : "f"(x));
    return r;
}
__device__ __forceinline__ ull pack2(float lo, float hi) {
    ull r;
    asm("mov.b64 %0, {%1, %2};" : "=l"(r) : "f"(lo), "f"(hi));
    return r;
}
__device__ __forceinline__ void unpack2(ull v, float& lo, float& hi) {
    asm("mov.b64 {%0, %1}, %2;" : "=f"(lo), "=f"(hi) : "l"(v));
}

// ---- cp.async double-buffer helpers ----
__device__ __forceinline__ void cpa16(uint32_t s, const float* g) {
    asm volatile("cp.async.cg.shared.global [%0], [%1], 16;" :: "r"(s), "l"(g));
}
__device__ __forceinline__ void cp_commit() { asm volatile("cp.async.commit_group;"); }
template <int N>
__device__ __forceinline__ void cp_wait() { asm volatile("cp.async.wait_group %0;" :: "n"(N)); }

// smem layout per buffer (floats)
constexpr int SM_BIAS1 = 0, SM_COS1 = 16, SM_SIN1 = 272;
constexpr int SM_BIAS2 = 528, SM_COS2 = 544, SM_SIN2 = 800;
constexpr int SMEM_FLOATS = 1056;

}  // namespace

// Split-K partial sums: [seg][b*CO*16 + j*16 + p*4 + r]
__device__ float g_partial[NSEG * OUT_ELEMS];

// CTA = (b-block of 256, j, i-segment). Thread = 2 batches (b, b+128) for one j.
__global__ void __launch_bounds__(128) nro_kernel(
    const float* __restrict__ F,     // (B, CI, 4, 4)
    const float* __restrict__ theta, // (B, CJ)
    const float* __restrict__ Wb,    // (CO, CI, 4, 4)
    const float* __restrict__ Wc,    // (CO, CI, CJ, 4, 4)
    const float* __restrict__ Ws,    // (CO, CI, CJ, 4, 4)
    const float* __restrict__ Wbb,   // (CO, CI, 4, 4)
    const float* __restrict__ Wbc,   // (CO, CI, CJ, 4, 4)
    const float* __restrict__ Wbs)   // (CO, CI, CJ, 4, 4)
{
    __shared__ __align__(16) float sm[2][SMEM_FLOATS];

    const int tid = threadIdx.x;
    const int j   = blockIdx.y;
    const int seg = blockIdx.z;
    const int i0  = seg * ISEG;
    const int b0  = blockIdx.x * 256 + tid;   // batch 0
    const int b1  = b0 + 128;                 // batch 1

    // Per-thread trig (scalar floats; splat on use)
    float tc[NB][CJ], ts[NB][CJ];
#pragma unroll
    for (int c = 0; c < CJ; c++) {
        sincosf(theta[b0 * CJ + c], &ts[0][c], &tc[0][c]);
        sincosf(theta[b1 * CJ + c], &ts[1][c], &tc[1][c]);
    }

    // Accumulators per batch: a01[n][p] = {out[p][0],out[p][1]}, a23 = {[2],[3]}
    ull a01[NB][4], a23[NB][4];
#pragma unroll
    for (int n = 0; n < NB; n++)
#pragma unroll
        for (int p = 0; p < 4; p++) { a01[n][p] = 0ull; a23[n][p] = 0ull; }

    auto preload = [&](int buf, int i) {
        float* s = sm[buf];
        uint32_t sa = (uint32_t)__cvta_generic_to_shared(s);
        const int o256 = (j * CI + i) * 256;
        const int o16  = (j * CI + i) * 16;
#pragma unroll
        for (int x = tid; x < 256; x += 128) {
            const int segm = x >> 6;
            const int w    = (x & 63) << 2;
            const float* g = (segm == 0) ? (Wc  + o256 + w)
                           : (segm == 1) ? (Ws  + o256 + w)
                           : (segm == 2) ? (Wbc + o256 + w)
                                         : (Wbs + o256 + w);
            const int so = (segm == 0) ? SM_COS1 : (segm == 1) ? SM_SIN1
                         : (segm == 2) ? SM_COS2 : SM_SIN2;
            cpa16(sa + (uint32_t)(so + w) * 4u, g);
        }
        if (tid < 8) {
            const float* g = ((tid < 4) ? Wb : Wbb) + o16 + (tid & 3) * 4;
            const int so   = ((tid < 4) ? SM_BIAS1 : SM_BIAS2) + (tid & 3) * 4;
            cpa16(sa + (uint32_t)so * 4u, g);
        }
    };

    preload(0, i0);
    cp_commit();

    for (int ii = 0; ii < ISEG; ii++) {
        const int i   = i0 + ii;
        const int cur = ii & 1;
        if (ii + 1 < ISEG) {
            preload(cur ^ 1, i + 1);
            cp_commit();
            cp_wait<1>();
        } else {
            cp_wait<0>();
        }
        __syncthreads();

        // F[b,i,:,:] for both batches
        float fr[NB][4][4];
#pragma unroll
        for (int n = 0; n < NB; n++) {
            const int bb = (n == 0) ? b0 : b1;
            const float4* Fp = (const float4*)(F + (bb * CI + i) * 16);
#pragma unroll
            for (int p = 0; p < 4; p++) {
                float4 f = Fp[p];
                fr[n][p][0] = f.x; fr[n][p][1] = f.y;
                fr[n][p][2] = f.z; fr[n][p][3] = f.w;
            }
        }

        const float* s = sm[cur];
        const ulonglong2* bw1 = (const ulonglong2*)(s + SM_BIAS1);
        const ulonglong2* cw1 = (const ulonglong2*)(s + SM_COS1);
        const ulonglong2* sw1 = (const ulonglong2*)(s + SM_SIN1);
        const ulonglong2* bw2 = (const ulonglong2*)(s + SM_BIAS2);
        const ulonglong2* cw2 = (const ulonglong2*)(s + SM_COS2);
        const ulonglong2* sw2 = (const ulonglong2*)(s + SM_SIN2);

        // ---- term1: build U per batch, apply out[p][r] += sum_q F[p][q]*U[q][r]
        {
            ull u01[NB][4], u23[NB][4];
#pragma unroll
            for (int r = 0; r < 4; r++) {
                ulonglong2 x = bw1[r];
#pragma unroll
                for (int n = 0; n < NB; n++) { u01[n][r] = x.x; u23[n][r] = x.y; }
            }
#pragma unroll
            for (int c = 0; c < CJ; c++) {
                ull vc0 = splat2(tc[0][c]), vs0 = splat2(ts[0][c]);
                ull vc1 = splat2(tc[1][c]), vs1 = splat2(ts[1][c]);
#pragma unroll
                for (int r = 0; r < 4; r++) {
                    ulonglong2 w;
                    w = cw1[c * 4 + r];
                    u01[0][r] = fma2(w.x, vc0, u01[0][r]);
                    u23[0][r] = fma2(w.y, vc0, u23[0][r]);
                    u01[1][r] = fma2(w.x, vc1, u01[1][r]);
                    u23[1][r] = fma2(w.y, vc1, u23[1][r]);
                    w = sw1[c * 4 + r];
                    u01[0][r] = fma2(w.x, vs0, u01[0][r]);
                    u23[0][r] = fma2(w.y, vs0, u23[0][r]);
                    u01[1][r] = fma2(w.x, vs1, u01[1][r]);
                    u23[1][r] = fma2(w.y, vs1, u23[1][r]);
                }
            }
#pragma unroll
            for (int n = 0; n < NB; n++)
#pragma unroll
                for (int p = 0; p < 4; p++)
#pragma unroll
                    for (int q = 0; q < 4; q++) {
                        ull fs = splat2(fr[n][p][q]);
                        a01[n][p] = fma2(fs, u01[n][q], a01[n][p]);
                        a23[n][p] = fma2(fs, u23[n][q], a23[n][p]);
                    }
        }

        // ---- term2: build Ub per batch, apply out[p][r] += sum_q Ub[p][q]*F[q][r]
        {
            ull t01[NB][4], t23[NB][4];
#pragma unroll
            for (int r = 0; r < 4; r++) {
                ulonglong2 x = bw2[r];
#pragma unroll
                for (int n = 0; n < NB; n++) { t01[n][r] = x.x; t23[n][r] = x.y; }
            }
#pragma unroll
            for (int c = 0; c < CJ; c++) {
                ull vc0 = splat2(tc[0][c]), vs0 = splat2(ts[0][c]);
                ull vc1 = splat2(tc[1][c]), vs1 = splat2(ts[1][c]);
#pragma unroll
                for (int r = 0; r < 4; r++) {
                    ulonglong2 w;
                    w = cw2[c * 4 + r];
                    t01[0][r] = fma2(w.x, vc0, t01[0][r]);
                    t23[0][r] = fma2(w.y, vc0, t23[0][r]);
                    t01[1][r] = fma2(w.x, vc1, t01[1][r]);
                    t23[1][r] = fma2(w.y, vc1, t23[1][r]);
                    w = sw2[c * 4 + r];
                    t01[0][r] = fma2(w.x, vs0, t01[0][r]);
                    t23[0][r] = fma2(w.y, vs0, t23[0][r]);
                    t01[1][r] = fma2(w.x, vs1, t01[1][r]);
                    t23[1][r] = fma2(w.y, vs1, t23[1][r]);
                }
            }
#pragma unroll
            for (int n = 0; n < NB; n++) {
                ull f01[4], f23[4];
#pragma unroll
                for (int q = 0; q < 4; q++) {
                    f01[q] = pack2(fr[n][q][0], fr[n][q][1]);
                    f23[q] = pack2(fr[n][q][2], fr[n][q][3]);
                }
#pragma unroll
                for (int p = 0; p < 4; p++) {
                    float g0, g1, g2, g3;
                    unpack2(t01[n][p], g0, g1);
                    unpack2(t23[n][p], g2, g3);
                    const float gg[4] = {g0, g1, g2, g3};
#pragma unroll
                    for (int q = 0; q < 4; q++) {
                        ull gs = splat2(gg[q]);
                        a01[n][p] = fma2(gs, f01[n == 0 ? q : q], a01[n][p]);
                        a23[n][p] = fma2(gs, f23[q], a23[n][p]);
                    }
                }
            }
        }

        __syncthreads();  // protect 'cur' buffer before next preload overwrite
    }

    // partial write: g_partial[seg][(b*CO + j)*16 + ...]
#pragma unroll
    for (int n = 0; n < NB; n++) {
        const int bb = (n == 0) ? b0 : b1;
        float4* op = (float4*)(g_partial + seg * OUT_ELEMS + (bb * CO + j) * 16);
#pragma unroll
        for (int p = 0; p < 4; p++) {
            float4 o;
            unpack2(a01[n][p], o.x, o.y);
            unpack2(a23[n][p], o.z, o.w);
            op[p] = o;
        }
    }
}

// Sum the NSEG partials into d_out (vectorized, deterministic fixed order).
__global__ void __launch_bounds__(256) nro_reduce(float* __restrict__ out) {
    const int idx = blockIdx.x * 256 + threadIdx.x;  // float4 index
    const float4* p0 = (const float4*)(g_partial + 0 * OUT_ELEMS);
    const float4* p1 = (const float4*)(g_partial + 1 * OUT_ELEMS);
    const float4* p2 = (const float4*)(g_partial + 2 * OUT_ELEMS);
    const float4* p3 = (const float4*)(g_partial + 3 * OUT_ELEMS);
    float4 a = p0[idx], b = p1[idx], c = p2[idx], d = p3[idx];
    float4 o;
    o.x = (a.x + b.x) + (c.x + d.x);
    o.y = (a.y + b.y) + (c.y + d.y);
    o.z = (a.z + b.z) + (c.z + d.z);
    o.w = (a.w + b.w) + (c.w + d.w);
    ((float4*)out)[idx] = o;
}

extern "C" void kernel_launch(void* const* d_in, const int* in_sizes, int n_in,
                              void* d_out, int out_size) {
    (void)in_sizes; (void)n_in; (void)out_size;
    const float* F   = (const float*)d_in[0];
    const float* th  = (const float*)d_in[1];
    const float* Wb  = (const float*)d_in[2];
    const float* Wc  = (const float*)d_in[3];
    const float* Ws  = (const float*)d_in[4];
    const float* Wbb = (const float*)d_in[5];
    const float* Wbc = (const float*)d_in[6];
    const float* Wbs = (const float*)d_in[7];

    dim3 grid(2, 64, NSEG);  // (b-blocks of 256, j, i-segments)
    nro_kernel<<<grid, 128>>>(F, th, Wb, Wc, Ws, Wbb, Wbc, Wbs);
    nro_reduce<<<OUT_ELEMS / 4 / 256, 256>>>((float*)d_out);
}

// round 4
// speedup vs baseline: 2.3232x; 1.7245x over previous
#include <cuda_runtime.h>
#include <cstdint>

// ============================================================================
// Problem constants
// ============================================================================
namespace {
constexpr int CI = 64, CO = 64, CJ = 16, B_ = 512;
constexpr int HC   = 16;          // i-chunks of 4
constexpr int KT   = 5;           // k-tiles of 8 (K = 40, real 33: bias + 16cos + 16sin)
constexpr int USTRIDE = 68;       // floats per b-row in Us/Fs (64 + 4 pad; 17 float4s, odd -> conflict-free)
constexpr int SMEM_HALF = 128 * USTRIDE;            // 8704 floats
constexpr int SMEM_DYN  = 2 * SMEM_HALF * 4;        // 69632 bytes
using ull = unsigned long long;
}

// Prepped operands (device globals; no allocation)
// A fragments: [term][j][hc][kt][mt(4)][lane(32)][4]  (tf32 bits)
__device__ uint32_t g_wa[2 * 64 * HC * KT * 4 * 32 * 4];   // 5.24M u32 = 21MB
// B fragments: [bt(4)][nt(16)][kt(5)][lane(32)] x uint2  (tf32 bits)
__device__ uint32_t g_vb[4 * 16 * KT * 32 * 2];            // 20480 u32

// ============================================================================
// helpers
// ============================================================================
__device__ __forceinline__ uint32_t f2tf32(float f) {
    uint32_t r;
    asm("cvt.rna.tf32.f32 %0, %1;" : "=r"(r) : "f"(f));
    return r;
}
__device__ __forceinline__ ull fma2(ull a, ull b, ull c) {
    ull d;
    asm("fma.rn.f32x2 %0, %1, %2, %3;" : "=l"(d) : "l"(a), "l"(b), "l"(c));
    return d;
}
__device__ __forceinline__ ull splat2(float x) {
    ull r;
    asm("mov.b64 %0, {%1, %1};" : "=l"(r) : "f"(x));
    return r;
}
__device__ __forceinline__ ull pack2(float lo, float hi) {
    ull r;
    asm("mov.b64 %0, {%1, %2};" : "=l"(r) : "f"(lo), "f"(hi));
    return r;
}
__device__ __forceinline__ void unpack2(ull v, float& lo, float& hi) {
    asm("mov.b64 {%0, %1}, %2;" : "=f"(lo), "=f"(hi) : "l"(v));
}
__device__ __forceinline__ void mma_tf32(float c[4], uint32_t a0, uint32_t a1,
                                         uint32_t a2, uint32_t a3,
                                         uint32_t b0, uint32_t b1) {
    asm volatile(
        "mma.sync.aligned.m16n8k8.row.col.f32.tf32.tf32.f32 "
        "{%0,%1,%2,%3}, {%4,%5,%6,%7}, {%8,%9}, {%0,%1,%2,%3};"
        : "+f"(c[0]), "+f"(c[1]), "+f"(c[2]), "+f"(c[3])
        : "r"(a0), "r"(a1), "r"(a2), "r"(a3), "r"(b0), "r"(b1));
}

// ============================================================================
// Prep 1: weight A-fragments.  block = (term, j, hc); 256 threads.
//   Row m (0..63) of the build GEMM = i_l*16 + rr, rr = q*4+r (t1) / p*4+q (t2)
//   -> within (j,i,c) both terms index the same flat rr. Column k: 0=bias,
//   1..16=cos(c), 17..32=sin(c), 33..39=zero pad.
//   Fragment layout per m16n8k8 A: a0(rr=g,k), a1(rr=g+8,k), a2(g,k+4), a3(g+8,k+4)
// ============================================================================
__global__ void __launch_bounds__(256) prep_w(
    const float* __restrict__ Wb,  const float* __restrict__ Wc,  const float* __restrict__ Ws,
    const float* __restrict__ Wbb, const float* __restrict__ Wbc, const float* __restrict__ Wbs)
{
    __shared__ float sB[4][16], sC[4][256], sS[4][256];
    const int bid  = blockIdx.x;
    const int term = bid >> 10;
    const int j    = (bid >> 4) & 63;
    const int hc   = bid & 15;
    const int i0   = hc * 4;
    const int t    = threadIdx.x;

    const float* pB = term ? Wbb : Wb;
    const float* pC = term ? Wbc : Wc;
    const float* pS = term ? Wbs : Ws;

    if (t < 16) ((float4*)sB)[t] = ((const float4*)(pB + (size_t)(j * 64 + i0) * 16))[t];
    ((float4*)sC)[t] = ((const float4*)(pC + (size_t)(j * 64 + i0) * 256))[t];
    ((float4*)sS)[t] = ((const float4*)(pS + (size_t)(j * 64 + i0) * 256))[t];
    __syncthreads();

    auto wval = [&](int i, int rr, int k) -> float {
        if (k == 0)  return sB[i][rr];
        if (k <= 16) return sC[i][(k - 1) * 16 + rr];
        if (k <= 32) return sS[i][(k - 17) * 16 + rr];
        return 0.0f;
    };

    for (int e = t; e < KT * 4 * 32; e += 256) {
        const int lane = e & 31, mt = (e >> 5) & 3, kt = e >> 7;
        const int rr = lane >> 2, k = kt * 8 + (lane & 3);
        uint4 o;
        o.x = f2tf32(wval(mt, rr,     k));
        o.y = f2tf32(wval(mt, rr + 8, k));
        o.z = f2tf32(wval(mt, rr,     k + 4));
        o.w = f2tf32(wval(mt, rr + 8, k + 4));
        ((uint4*)g_wa)[((bid * KT + kt) * 4 + mt) * 32 + lane] = o;
    }
}

// ============================================================================
// Prep 2: trig B-fragments.  v[k,b]: k0=1, 1..16 cos, 17..32 sin, pad 0.
//   Fragment per m16n8k8 B: b0(k=lane&3, n=lane>>2), b1(k+4, n)
// ============================================================================
__global__ void __launch_bounds__(256) prep_v(const float* __restrict__ theta) {
    const int t = blockIdx.x * 256 + threadIdx.x;   // 10240 total
    const int lane = t & 31;
    const int kt   = (t >> 5) % KT;
    const int nt   = (t / (32 * KT)) & 15;
    const int bt   = t / (32 * KT * 16);
    const int b    = bt * 128 + nt * 8 + (lane >> 2);
    const int k0   = kt * 8 + (lane & 3);

    auto vval = [&](int k) -> float {
        if (k == 0)  return 1.0f;
        if (k <= 16) return cosf(theta[b * CJ + (k - 1)]);
        if (k <= 32) return sinf(theta[b * CJ + (k - 17)]);
        return 0.0f;
    };
    uint2 o;
    o.x = f2tf32(vval(k0));
    o.y = f2tf32(vval(k0 + 4));
    ((uint2*)g_vb)[((bt * 16 + nt) * KT + kt) * 32 + lane] = o;
}

// ============================================================================
// Main: per CTA (btile of 128 b, j). Per i-chunk of 4 and per term:
//   1) mma.sync builds U[(i,q,r) | (i,p,q)][b] over K=40 (A,B from gmem frags)
//   2) C-frags -> smem Us[b][m] (stride 68)
//   3) f32x2 apply from Us + staged Fs, accumulate out[b,j,p,r] in regs.
// ============================================================================
__global__ void __launch_bounds__(256, 2) main_kernel(
    const float* __restrict__ F,   // (B, CI, 4, 4)
    float* __restrict__ out)       // (B, CO, 4, 4)
{
    extern __shared__ float sm[];
    float* Us = sm;
    float* Fs = sm + SMEM_HALF;

    const int tid  = threadIdx.x;
    const int wid  = tid >> 5;
    const int lane = tid & 31;
    const int bt   = blockIdx.x;
    const int j    = blockIdx.y;
    const int wm   = wid & 1;       // warp M-block (2 x M32)
    const int wn   = wid >> 1;      // warp N-block (4 x N32)
    const int gid  = lane >> 2;
    const int tig  = lane & 3;
    const int b_l  = tid & 127;     // apply: thread's batch
    const int p0   = (tid >> 7) * 2;  // apply: thread's p pair

    ull o01[2] = {0ull, 0ull}, o23[2] = {0ull, 0ull};

    const uint4* Aw = (const uint4*)g_wa;
    const uint2* Vb = (const uint2*)g_vb;

    for (int hc = 0; hc < HC; hc++) {
        __syncthreads();   // Fs + Us free (previous applies done)

        // ---- stage Fs[b][x], x = i_l*16 + p*4 + q  (coalesced LDG + STS) ----
#pragma unroll
        for (int pass = 0; pass < 8; pass++) {
            const int v  = pass * 256 + tid;       // 2048 float4s
            const int bb = v >> 4;
            const int x  = v & 15;
            const float4 f = ((const float4*)F)[(size_t)(bt * 128 + bb) * 256 +
                                                (hc * 4 + (x >> 2)) * 4 + (x & 3)];
            *(float4*)(Fs + bb * USTRIDE + x * 4) = f;
        }

#pragma unroll
        for (int term = 0; term < 2; term++) {
            // ---- build: 8 mma-tiles (M32 x N32) x 5 k-steps, operands from gmem
            float c[2][4][4];
#pragma unroll
            for (int fm = 0; fm < 2; fm++)
#pragma unroll
                for (int fn = 0; fn < 4; fn++)
#pragma unroll
                    for (int e = 0; e < 4; e++) c[fm][fn][e] = 0.0f;

            const int abid = (term * 1024 + j * 16 + hc) * KT;
#pragma unroll
            for (int kt = 0; kt < KT; kt++) {
                uint4 a[2];
                a[0] = Aw[(abid + kt) * 4 * 32 + (wm * 2 + 0) * 32 + lane];
                a[1] = Aw[(abid + kt) * 4 * 32 + (wm * 2 + 1) * 32 + lane];
                uint2 bf[4];
#pragma unroll
                for (int fn = 0; fn < 4; fn++)
                    bf[fn] = Vb[((bt * 16 + wn * 4 + fn) * KT + kt) * 32 + lane];
#pragma unroll
                for (int fm = 0; fm < 2; fm++)
#pragma unroll
                    for (int fn = 0; fn < 4; fn++)
                        mma_tf32(c[fm][fn], a[fm].x, a[fm].y, a[fm].z, a[fm].w,
                                 bf[fn].x, bf[fn].y);
            }

            __syncthreads();   // staging STS visible; Us free (prev apply done)

            // ---- C-frags -> Us[b][m], stride 68 (conflict-free scalar stores)
#pragma unroll
            for (int fm = 0; fm < 2; fm++)
#pragma unroll
                for (int fn = 0; fn < 4; fn++) {
                    const int m = (wm * 2 + fm) * 16 + gid;
                    const int n = (wn * 4 + fn) * 8 + 2 * tig;
                    Us[n * USTRIDE + m]           = c[fm][fn][0];
                    Us[(n + 1) * USTRIDE + m]     = c[fm][fn][1];
                    Us[n * USTRIDE + m + 8]       = c[fm][fn][2];
                    Us[(n + 1) * USTRIDE + m + 8] = c[fm][fn][3];
                }
            __syncthreads();

            // ---- apply ----
            const float* ub = Us + b_l * USTRIDE;
            const float* fb = Fs + b_l * USTRIDE;
            if (term == 0) {
                // out[p][r] += sum_q F[p][q] * U[(i,q,r)]
#pragma unroll
                for (int il = 0; il < 4; il++) {
                    ulonglong2 uq[4];
#pragma unroll
                    for (int q = 0; q < 4; q++)
                        uq[q] = *(const ulonglong2*)(ub + il * 16 + q * 4);
#pragma unroll
                    for (int pp = 0; pp < 2; pp++) {
                        const float4 f = *(const float4*)(fb + il * 16 + (p0 + pp) * 4);
                        const float fv[4] = {f.x, f.y, f.z, f.w};
#pragma unroll
                        for (int q = 0; q < 4; q++) {
                            const ull fs = splat2(fv[q]);
                            o01[pp] = fma2(fs, uq[q].x, o01[pp]);
                            o23[pp] = fma2(fs, uq[q].y, o23[pp]);
                        }
                    }
                }
            } else {
                // out[p][r] += sum_q Ub[(i,p,q)] * F[q][r]
#pragma unroll
                for (int il = 0; il < 4; il++) {
                    ull f01[4], f23[4];
#pragma unroll
                    for (int q = 0; q < 4; q++) {
                        const float4 fq = *(const float4*)(fb + il * 16 + q * 4);
                        f01[q] = pack2(fq.x, fq.y);
                        f23[q] = pack2(fq.z, fq.w);
                    }
#pragma unroll
                    for (int pp = 0; pp < 2; pp++) {
                        const float4 u = *(const float4*)(ub + il * 16 + (p0 + pp) * 4);
                        const float uv[4] = {u.x, u.y, u.z, u.w};
#pragma unroll
                        for (int q = 0; q < 4; q++) {
                            const ull gs = splat2(uv[q]);
                            o01[pp] = fma2(gs, f01[q], o01[pp]);
                            o23[pp] = fma2(gs, f23[q], o23[pp]);
                        }
                    }
                }
            }
        }
    }

    // ---- final write: out[b, j, p, 0..3] for p = p0, p0+1 ----
#pragma unroll
    for (int pp = 0; pp < 2; pp++) {
        float4 o;
        unpack2(o01[pp], o.x, o.y);
        unpack2(o23[pp], o.z, o.w);
        ((float4*)out)[(size_t)((bt * 128 + b_l) * 64 + j) * 4 + (p0 + pp)] = o;
    }
}

// ============================================================================
// Launch
// ============================================================================
extern "C" void kernel_launch(void* const* d_in, const int* in_sizes, int n_in,
                              void* d_out, int out_size) {
    (void)in_sizes; (void)n_in; (void)out_size;
    const float* F   = (const float*)d_in[0];
    const float* th  = (const float*)d_in[1];
    const float* Wb  = (const float*)d_in[2];
    const float* Wc  = (const float*)d_in[3];
    const float* Ws  = (const float*)d_in[4];
    const float* Wbb = (const float*)d_in[5];
    const float* Wbc = (const float*)d_in[6];
    const float* Wbs = (const float*)d_in[7];

    cudaFuncSetAttribute(main_kernel, cudaFuncAttributeMaxDynamicSharedMemorySize, SMEM_DYN);

    prep_w<<<2 * 64 * HC, 256>>>(Wb, Wc, Ws, Wbb, Wbc, Wbs);
    prep_v<<<40, 256>>>(th);
    main_kernel<<<dim3(4, 64), 256, SMEM_DYN>>>(F, (float*)d_out);
}

// round 5
// speedup vs baseline: 2.6468x; 1.1393x over previous
#include <cuda_runtime.h>
#include <cstdint>

// ============================================================================
// Problem constants
// ============================================================================
namespace {
constexpr int CI = 64, CO = 64, CJ = 16, B_ = 512;
constexpr int HC   = 16;          // i-chunks of 4
constexpr int KT   = 5;           // k-tiles of 8 (K = 40, real 33: bias + 16cos + 16sin)
constexpr int USTRIDE = 68;       // floats per b-row in Us/Fs (64 + 4 pad)
constexpr int SMEM_HALF = 128 * USTRIDE;            // 8704 floats
constexpr int A_STEP_U4 = KT * 4 * 32;              // 640 uint4 per (hc,term) step
constexpr int A_STEP_FL = A_STEP_U4 * 4;            // 2560 floats
constexpr int SMEM_FLOATS = 2 * SMEM_HALF + 2 * A_STEP_FL;   // 22528
constexpr int SMEM_DYN  = SMEM_FLOATS * 4;                   // 90112 bytes
using ull = unsigned long long;
}

// Prepped operands (device globals; no allocation)
// A fragments: [term][j][hc][kt][mt(4)][lane(32)][4]  (tf32 bits)
__device__ uint32_t g_wa[2 * 64 * HC * KT * 4 * 32 * 4];   // 21MB
// B fragments: [bt(4)][nt(16)][kt(5)][lane(32)] x uint2  (tf32 bits)
__device__ uint32_t g_vb[4 * 16 * KT * 32 * 2];

// ============================================================================
// helpers
// ============================================================================
__device__ __forceinline__ uint32_t f2tf32(float f) {
    uint32_t r;
    asm("cvt.rna.tf32.f32 %0, %1;" : "=r"(r) : "f"(f));
    return r;
}
__device__ __forceinline__ ull fma2(ull a, ull b, ull c) {
    ull d;
    asm("fma.rn.f32x2 %0, %1, %2, %3;" : "=l"(d) : "l"(a), "l"(b), "l"(c));
    return d;
}
__device__ __forceinline__ ull splat2(float x) {
    ull r;
    asm("mov.b64 %0, {%1, %1};" : "=l"(r) : "f"(x));
    return r;
}
__device__ __forceinline__ ull pack2(float lo, float hi) {
    ull r;
    asm("mov.b64 %0, {%1, %2};" : "=l"(r) : "f"(lo), "f"(hi));
    return r;
}
__device__ __forceinline__ void unpack2(ull v, float& lo, float& hi) {
    asm("mov.b64 {%0, %1}, %2;" : "=f"(lo), "=f"(hi) : "l"(v));
}
__device__ __forceinline__ void mma_tf32(float c[4], uint32_t a0, uint32_t a1,
                                         uint32_t a2, uint32_t a3,
                                         uint32_t b0, uint32_t b1) {
    asm volatile(
        "mma.sync.aligned.m16n8k8.row.col.f32.tf32.tf32.f32 "
        "{%0,%1,%2,%3}, {%4,%5,%6,%7}, {%8,%9}, {%0,%1,%2,%3};"
        : "+f"(c[0]), "+f"(c[1]), "+f"(c[2]), "+f"(c[3])
        : "r"(a0), "r"(a1), "r"(a2), "r"(a3), "r"(b0), "r"(b1));
}
__device__ __forceinline__ void cpa16(uint32_t s, const void* g) {
    asm volatile("cp.async.cg.shared.global [%0], [%1], 16;" :: "r"(s), "l"(g));
}
__device__ __forceinline__ void cp_commit() { asm volatile("cp.async.commit_group;"); }
template <int N>
__device__ __forceinline__ void cp_wait() { asm volatile("cp.async.wait_group %0;" :: "n"(N)); }

// ============================================================================
// Prep 1: weight A-fragments (unchanged from R4)
// ============================================================================
__global__ void __launch_bounds__(256) prep_w(
    const float* __restrict__ Wb,  const float* __restrict__ Wc,  const float* __restrict__ Ws,
    const float* __restrict__ Wbb, const float* __restrict__ Wbc, const float* __restrict__ Wbs)
{
    __shared__ float sB[4][16], sC[4][256], sS[4][256];
    const int bid  = blockIdx.x;
    const int term = bid >> 10;
    const int j    = (bid >> 4) & 63;
    const int hc   = bid & 15;
    const int i0   = hc * 4;
    const int t    = threadIdx.x;

    const float* pB = term ? Wbb : Wb;
    const float* pC = term ? Wbc : Wc;
    const float* pS = term ? Wbs : Ws;

    if (t < 16) ((float4*)sB)[t] = ((const float4*)(pB + (size_t)(j * 64 + i0) * 16))[t];
    ((float4*)sC)[t] = ((const float4*)(pC + (size_t)(j * 64 + i0) * 256))[t];
    ((float4*)sS)[t] = ((const float4*)(pS + (size_t)(j * 64 + i0) * 256))[t];
    __syncthreads();

    auto wval = [&](int i, int rr, int k) -> float {
        if (k == 0)  return sB[i][rr];
        if (k <= 16) return sC[i][(k - 1) * 16 + rr];
        if (k <= 32) return sS[i][(k - 17) * 16 + rr];
        return 0.0f;
    };

    for (int e = t; e < KT * 4 * 32; e += 256) {
        const int lane = e & 31, mt = (e >> 5) & 3, kt = e >> 7;
        const int rr = lane >> 2, k = kt * 8 + (lane & 3);
        uint4 o;
        o.x = f2tf32(wval(mt, rr,     k));
        o.y = f2tf32(wval(mt, rr + 8, k));
        o.z = f2tf32(wval(mt, rr,     k + 4));
        o.w = f2tf32(wval(mt, rr + 8, k + 4));
        ((uint4*)g_wa)[((bid * KT + kt) * 4 + mt) * 32 + lane] = o;
    }
}

// ============================================================================
// Prep 2: trig B-fragments (unchanged from R4)
// ============================================================================
__global__ void __launch_bounds__(256) prep_v(const float* __restrict__ theta) {
    const int t = blockIdx.x * 256 + threadIdx.x;
    const int lane = t & 31;
    const int kt   = (t >> 5) % KT;
    const int nt   = (t / (32 * KT)) & 15;
    const int bt   = t / (32 * KT * 16);
    const int b    = bt * 128 + nt * 8 + (lane >> 2);
    const int k0   = kt * 8 + (lane & 3);

    auto vval = [&](int k) -> float {
        if (k == 0)  return 1.0f;
        if (k <= 16) return cosf(theta[b * CJ + (k - 1)]);
        if (k <= 32) return sinf(theta[b * CJ + (k - 17)]);
        return 0.0f;
    };
    uint2 o;
    o.x = f2tf32(vval(k0));
    o.y = f2tf32(vval(k0 + 4));
    ((uint2*)g_vb)[((bt * 16 + nt) * KT + kt) * 32 + lane] = o;
}

// ============================================================================
// Main kernel
// ============================================================================
__global__ void __launch_bounds__(256, 2) main_kernel(
    const float* __restrict__ F,   // (B, CI, 4, 4)
    float* __restrict__ out)       // (B, CO, 4, 4)
{
    extern __shared__ float sm[];
    float* Us = sm;
    float* Fs = sm + SMEM_HALF;
    float* A0 = sm + 2 * SMEM_HALF;           // A-frag double buffer
    float* A1 = A0 + A_STEP_FL;

    const int tid  = threadIdx.x;
    const int wid  = tid >> 5;
    const int lane = tid & 31;
    const int bt   = blockIdx.x;
    const int j    = blockIdx.y;
    const int wm   = wid & 1;       // warp M-block (2 x M32)
    const int wn   = wid >> 1;      // warp N-block (4 x N32)
    const int gid  = lane >> 2;
    const int tig  = lane & 3;
    const int b_l  = tid & 127;     // apply: thread's batch
    const int p0   = (tid >> 7) * 2;

    ull o01[2] = {0ull, 0ull}, o23[2] = {0ull, 0ull};

    // ---- hoist Vb fragments to registers (invariant over hc/term) ----
    uint2 vb[KT][4];
    {
        const uint2* Vb = (const uint2*)g_vb;
#pragma unroll
        for (int kt = 0; kt < KT; kt++)
#pragma unroll
            for (int fn = 0; fn < 4; fn++)
                vb[kt][fn] = Vb[((bt * 16 + wn * 4 + fn) * KT + kt) * 32 + lane];
    }

    // ---- A-fragment prefetch machinery ----
    // step s = hc*2 + term; slice base (uint4) = ((term*1024 + j*16 + hc)*KT)*4*32
    auto prefetch_A = [&](int s, float* dst) {
        const int term = s & 1, hc = s >> 1;
        const uint4* src = ((const uint4*)g_wa) + (size_t)((term * 1024 + j * 16 + hc) * KT) * 128;
        const uint32_t sa = (uint32_t)__cvta_generic_to_shared(dst);
#pragma unroll
        for (int e = tid; e < A_STEP_U4; e += 256)
            cpa16(sa + (uint32_t)e * 16u, src + e);
    };

    prefetch_A(0, A0);
    cp_commit();

    for (int hc = 0; hc < HC; hc++) {
#pragma unroll
        for (int term = 0; term < 2; term++) {
            const int s = hc * 2 + term;
            if (s + 1 < 32) {
                prefetch_A(s + 1, (s & 1) ? A0 : A1);  // other buffer
                cp_commit();
                cp_wait<1>();    // A(s) landed for this thread
            } else {
                cp_wait<0>();
            }
            __syncthreads();     // A(s) visible; prev apply done with Us/Fs

            // ---- stage Fs once per hc (overlaps with mma below) ----
            if (term == 0) {
#pragma unroll
                for (int pass = 0; pass < 8; pass++) {
                    const int v  = pass * 256 + tid;
                    const int bb = v >> 4;
                    const int x  = v & 15;
                    const float4 f = ((const float4*)F)[(size_t)(bt * 128 + bb) * 256 +
                                                        (hc * 4 + (x >> 2)) * 4 + (x & 3)];
                    *(float4*)(Fs + bb * USTRIDE + x * 4) = f;
                }
            }

            // ---- build: mma from smem A + register Vb ----
            float c[2][4][4];
#pragma unroll
            for (int fm = 0; fm < 2; fm++)
#pragma unroll
                for (int fn = 0; fn < 4; fn++)
#pragma unroll
                    for (int e = 0; e < 4; e++) c[fm][fn][e] = 0.0f;

            const uint4* As = (const uint4*)((s & 1) ? A1 : A0);
#pragma unroll
            for (int kt = 0; kt < KT; kt++) {
                uint4 a[2];
                a[0] = As[(kt * 4 + wm * 2 + 0) * 32 + lane];
                a[1] = As[(kt * 4 + wm * 2 + 1) * 32 + lane];
#pragma unroll
                for (int fm = 0; fm < 2; fm++)
#pragma unroll
                    for (int fn = 0; fn < 4; fn++)
                        mma_tf32(c[fm][fn], a[fm].x, a[fm].y, a[fm].z, a[fm].w,
                                 vb[kt][fn].x, vb[kt][fn].y);
            }

            __syncthreads();     // all warps done reading A(s) and prev Us

            // ---- C-frags -> Us[b][m], stride 68 ----
#pragma unroll
            for (int fm = 0; fm < 2; fm++)
#pragma unroll
                for (int fn = 0; fn < 4; fn++) {
                    const int m = (wm * 2 + fm) * 16 + gid;
                    const int n = (wn * 4 + fn) * 8 + 2 * tig;
                    Us[n * USTRIDE + m]           = c[fm][fn][0];
                    Us[(n + 1) * USTRIDE + m]     = c[fm][fn][1];
                    Us[n * USTRIDE + m + 8]       = c[fm][fn][2];
                    Us[(n + 1) * USTRIDE + m + 8] = c[fm][fn][3];
                }
            __syncthreads();

            // ---- apply ----
            const float* ub = Us + b_l * USTRIDE;
            const float* fb = Fs + b_l * USTRIDE;
            if (term == 0) {
                // out[p][r] += sum_q F[p][q] * U[(il,q,r)]
#pragma unroll
                for (int il = 0; il < 4; il++) {
                    ulonglong2 uq[4];
#pragma unroll
                    for (int q = 0; q < 4; q++)
                        uq[q] = *(const ulonglong2*)(ub + il * 16 + q * 4);
#pragma unroll
                    for (int pp = 0; pp < 2; pp++) {
                        const float4 f = *(const float4*)(fb + il * 16 + (p0 + pp) * 4);
                        const float fv[4] = {f.x, f.y, f.z, f.w};
#pragma unroll
                        for (int q = 0; q < 4; q++) {
                            const ull fs = splat2(fv[q]);
                            o01[pp] = fma2(fs, uq[q].x, o01[pp]);
                            o23[pp] = fma2(fs, uq[q].y, o23[pp]);
                        }
                    }
                }
            } else {
                // out[p][r] += sum_q Ub[(il,p,q)] * F[q][r]
#pragma unroll
                for (int il = 0; il < 4; il++) {
                    ull f01[4], f23[4];
#pragma unroll
                    for (int q = 0; q < 4; q++) {
                        const float4 fq = *(const float4*)(fb + il * 16 + q * 4);
                        f01[q] = pack2(fq.x, fq.y);
                        f23[q] = pack2(fq.z, fq.w);
                    }
#pragma unroll
                    for (int pp = 0; pp < 2; pp++) {
                        const float4 u = *(const float4*)(ub + il * 16 + (p0 + pp) * 4);
                        const float uv[4] = {u.x, u.y, u.z, u.w};
#pragma unroll
                        for (int q = 0; q < 4; q++) {
                            const ull gs = splat2(uv[q]);
                            o01[pp] = fma2(gs, f01[q], o01[pp]);
                            o23[pp] = fma2(gs, f23[q], o23[pp]);
                        }
                    }
                }
            }
        }
    }

    // ---- final write: out[b, j, p, 0..3] for p = p0, p0+1 ----
#pragma unroll
    for (int pp = 0; pp < 2; pp++) {
        float4 o;
        unpack2(o01[pp], o.x, o.y);
        unpack2(o23[pp], o.z, o.w);
        ((float4*)out)[(size_t)((bt * 128 + b_l) * 64 + j) * 4 + (p0 + pp)] = o;
    }
}

// ============================================================================
// Launch
// ============================================================================
extern "C" void kernel_launch(void* const* d_in, const int* in_sizes, int n_in,
                              void* d_out, int out_size) {
    (void)in_sizes; (void)n_in; (void)out_size;
    const float* F   = (const float*)d_in[0];
    const float* th  = (const float*)d_in[1];
    const float* Wb  = (const float*)d_in[2];
    const float* Wc  = (const float*)d_in[3];
    const float* Ws  = (const float*)d_in[4];
    const float* Wbb = (const float*)d_in[5];
    const float* Wbc = (const float*)d_in[6];
    const float* Wbs = (const float*)d_in[7];

    cudaFuncSetAttribute(main_kernel, cudaFuncAttributeMaxDynamicSharedMemorySize, SMEM_DYN);

    prep_w<<<2 * 64 * HC, 256>>>(Wb, Wc, Ws, Wbb, Wbc, Wbs);
    prep_v<<<40, 256>>>(th);
    main_kernel<<<dim3(4, 64), 256, SMEM_DYN>>>(F, (float*)d_out);
}

// round 6
// speedup vs baseline: 2.7757x; 1.0487x over previous
#include <cuda_runtime.h>
#include <cstdint>

// ============================================================================
// Problem constants
// ============================================================================
namespace {
constexpr int CI = 64, CO = 64, CJ = 16, B_ = 512;
constexpr int HC   = 16;          // i-chunks of 4
constexpr int KT   = 4;           // k-tiles of 8 (K = 32: 16 cos + 16 sin; bias via epilogue)
constexpr int USTRIDE = 68;       // floats per b-row in Us/Fs (64 + 4 pad)
constexpr int SMEM_HALF = 128 * USTRIDE;            // 8704 floats
constexpr int A_STEP_U4 = KT * 4 * 32;              // 512 uint4 per (hc,term) step
constexpr int A_STEP_FL = A_STEP_U4 * 4;            // 2048 floats
constexpr int SMEM_FLOATS = 2 * SMEM_HALF + 2 * A_STEP_FL;   // 21504
constexpr int SMEM_DYN  = SMEM_FLOATS * 4;                   // 86016 bytes
using ull = unsigned long long;
}

// Prepped operands (device globals; no allocation)
// A fragments: [term][j][hc][kt(4)][mt(4)][lane(32)][4]  (tf32 bits)
__device__ uint32_t g_wa[2 * 64 * HC * KT * 4 * 32 * 4];   // 16.8MB
// B fragments: [bt(4)][nt(16)][kt(4)][lane(32)] x uint2  (tf32 bits)
__device__ uint32_t g_vb[4 * 16 * KT * 32 * 2];

// ============================================================================
// helpers
// ============================================================================
__device__ __forceinline__ uint32_t f2tf32(float f) {
    uint32_t r;
    asm("cvt.rna.tf32.f32 %0, %1;" : "=r"(r) : "f"(f));
    return r;
}
__device__ __forceinline__ ull fma2(ull a, ull b, ull c) {
    ull d;
    asm("fma.rn.f32x2 %0, %1, %2, %3;" : "=l"(d) : "l"(a), "l"(b), "l"(c));
    return d;
}
__device__ __forceinline__ ull splat2(float x) {
    ull r;
    asm("mov.b64 %0, {%1, %1};" : "=l"(r) : "f"(x));
    return r;
}
__device__ __forceinline__ ull pack2(float lo, float hi) {
    ull r;
    asm("mov.b64 %0, {%1, %2};" : "=l"(r) : "f"(lo), "f"(hi));
    return r;
}
__device__ __forceinline__ void unpack2(ull v, float& lo, float& hi) {
    asm("mov.b64 {%0, %1}, %2;" : "=f"(lo), "=f"(hi) : "l"(v));
}
__device__ __forceinline__ void mma_tf32(float c[4], uint32_t a0, uint32_t a1,
                                         uint32_t a2, uint32_t a3,
                                         uint32_t b0, uint32_t b1) {
    asm volatile(
        "mma.sync.aligned.m16n8k8.row.col.f32.tf32.tf32.f32 "
        "{%0,%1,%2,%3}, {%4,%5,%6,%7}, {%8,%9}, {%0,%1,%2,%3};"
        : "+f"(c[0]), "+f"(c[1]), "+f"(c[2]), "+f"(c[3])
        : "r"(a0), "r"(a1), "r"(a2), "r"(a3), "r"(b0), "r"(b1));
}
__device__ __forceinline__ void cpa16(uint32_t s, const void* g) {
    asm volatile("cp.async.cg.shared.global [%0], [%1], 16;" :: "r"(s), "l"(g));
}
__device__ __forceinline__ void cp_commit() { asm volatile("cp.async.commit_group;"); }
template <int N>
__device__ __forceinline__ void cp_wait() { asm volatile("cp.async.wait_group %0;" :: "n"(N)); }

// ============================================================================
// Prep 1: weight A-fragments.  K = 32: k 0..15 = cos(c=k), 16..31 = sin(c=k-16)
// ============================================================================
__global__ void __launch_bounds__(256) prep_w(
    const float* __restrict__ Wc,  const float* __restrict__ Ws,
    const float* __restrict__ Wbc, const float* __restrict__ Wbs)
{
    __shared__ float sC[4][256], sS[4][256];
    const int bid  = blockIdx.x;
    const int term = bid >> 10;
    const int j    = (bid >> 4) & 63;
    const int hc   = bid & 15;
    const int i0   = hc * 4;
    const int t    = threadIdx.x;

    const float* pC = term ? Wbc : Wc;
    const float* pS = term ? Wbs : Ws;

    ((float4*)sC)[t] = ((const float4*)(pC + (size_t)(j * 64 + i0) * 256))[t];
    ((float4*)sS)[t] = ((const float4*)(pS + (size_t)(j * 64 + i0) * 256))[t];
    __syncthreads();

    auto wval = [&](int i, int rr, int k) -> float {
        return (k < 16) ? sC[i][k * 16 + rr] : sS[i][(k - 16) * 16 + rr];
    };

    for (int e = t; e < KT * 4 * 32; e += 256) {
        const int lane = e & 31, mt = (e >> 5) & 3, kt = e >> 7;
        const int rr = lane >> 2, k = kt * 8 + (lane & 3);
        uint4 o;
        o.x = f2tf32(wval(mt, rr,     k));
        o.y = f2tf32(wval(mt, rr + 8, k));
        o.z = f2tf32(wval(mt, rr,     k + 4));
        o.w = f2tf32(wval(mt, rr + 8, k + 4));
        ((uint4*)g_wa)[((bid * KT + kt) * 4 + mt) * 32 + lane] = o;
    }
}

// ============================================================================
// Prep 2: trig B-fragments.  v[k,b]: 0..15 cos, 16..31 sin.
// ============================================================================
__global__ void __launch_bounds__(256) prep_v(const float* __restrict__ theta) {
    const int t = blockIdx.x * 256 + threadIdx.x;   // 8192 total
    const int lane = t & 31;
    const int kt   = (t >> 5) & 3;
    const int nt   = (t >> 7) & 15;
    const int bt   = t >> 11;
    const int b    = bt * 128 + nt * 8 + (lane >> 2);
    const int k0   = kt * 8 + (lane & 3);

    auto vval = [&](int k) -> float {
        return (k < 16) ? cosf(theta[b * CJ + k]) : sinf(theta[b * CJ + (k - 16)]);
    };
    uint2 o;
    o.x = f2tf32(vval(k0));
    o.y = f2tf32(vval(k0 + 4));
    ((uint2*)g_vb)[((bt * 16 + nt) * KT + kt) * 32 + lane] = o;
}

// ============================================================================
// Main kernel
// ============================================================================
__global__ void __launch_bounds__(256, 2) main_kernel(
    const float* __restrict__ F,     // (B, CI, 4, 4)
    const float* __restrict__ Wb,    // (CO, CI, 4, 4)  -- bias term1, flat rr = q*4+r
    const float* __restrict__ Wbb,   // (CO, CI, 4, 4)  -- bias term2, flat rr = p*4+q
    float* __restrict__ out)         // (B, CO, 4, 4)
{
    extern __shared__ float sm[];
    float* Us = sm;
    float* Fs = sm + SMEM_HALF;
    float* A0 = sm + 2 * SMEM_HALF;           // A-frag double buffer
    float* A1 = A0 + A_STEP_FL;

    const int tid  = threadIdx.x;
    const int wid  = tid >> 5;
    const int lane = tid & 31;
    const int bt   = blockIdx.x;
    const int j    = blockIdx.y;
    const int wm   = wid & 1;       // warp M-block (2 x M32)
    const int wn   = wid >> 1;      // warp N-block (4 x N32)
    const int gid  = lane >> 2;
    const int tig  = lane & 3;
    // pairing: adjacent lanes share b_l (LDS broadcast), differ in p-half
    const int b_l  = tid >> 1;      // 0..127
    const int p0   = (tid & 1) * 2; // 0 or 2

    ull o01[2] = {0ull, 0ull}, o23[2] = {0ull, 0ull};

    // ---- hoist Vb fragments to registers (invariant over hc/term) ----
    uint2 vb[KT][4];
    {
        const uint2* Vb = (const uint2*)g_vb;
#pragma unroll
        for (int kt = 0; kt < KT; kt++)
#pragma unroll
            for (int fn = 0; fn < 4; fn++)
                vb[kt][fn] = Vb[((bt * 16 + wn * 4 + fn) * KT + kt) * 32 + lane];
    }

    // ---- A-fragment prefetch machinery ----
    auto prefetch_A = [&](int s, float* dst) {
        const int term = s & 1, hc = s >> 1;
        const uint4* src = ((const uint4*)g_wa) +
                           (size_t)((term * 1024 + j * 16 + hc) * KT) * 128;
        const uint32_t sa = (uint32_t)__cvta_generic_to_shared(dst);
#pragma unroll
        for (int e = tid; e < A_STEP_U4; e += 256)
            cpa16(sa + (uint32_t)e * 16u, src + e);
    };

    prefetch_A(0, A0);
    cp_commit();

    for (int hc = 0; hc < HC; hc++) {
#pragma unroll
        for (int term = 0; term < 2; term++) {
            const int s = hc * 2 + term;
            if (s + 1 < 32) {
                prefetch_A(s + 1, (s & 1) ? A0 : A1);
                cp_commit();
                cp_wait<1>();
            } else {
                cp_wait<0>();
            }
            __syncthreads();     // A(s) visible; prev apply done with Us/Fs

            // ---- stage Fs once per hc ----
            if (term == 0) {
#pragma unroll
                for (int pass = 0; pass < 8; pass++) {
                    const int v  = pass * 256 + tid;
                    const int bb = v >> 4;
                    const int x  = v & 15;
                    const float4 f = ((const float4*)F)[(size_t)(bt * 128 + bb) * 256 +
                                                        (hc * 4 + (x >> 2)) * 4 + (x & 3)];
                    *(float4*)(Fs + bb * USTRIDE + x * 4) = f;
                }
            }

            // ---- build: mma from smem A + register Vb (K = 32) ----
            float c[2][4][4];
#pragma unroll
            for (int fm = 0; fm < 2; fm++)
#pragma unroll
                for (int fn = 0; fn < 4; fn++)
#pragma unroll
                    for (int e = 0; e < 4; e++) c[fm][fn][e] = 0.0f;

            const uint4* As = (const uint4*)((s & 1) ? A1 : A0);
#pragma unroll
            for (int kt = 0; kt < KT; kt++) {
                uint4 a[2];
                a[0] = As[(kt * 4 + wm * 2 + 0) * 32 + lane];
                a[1] = As[(kt * 4 + wm * 2 + 1) * 32 + lane];
#pragma unroll
                for (int fm = 0; fm < 2; fm++)
#pragma unroll
                    for (int fn = 0; fn < 4; fn++)
                        mma_tf32(c[fm][fn], a[fm].x, a[fm].y, a[fm].z, a[fm].w,
                                 vb[kt][fn].x, vb[kt][fn].y);
            }

            // ---- add bias in fp32 (b-independent rows, direct from Wb/Wbb) ----
            {
                const float* bias = term ? Wbb : Wb;
#pragma unroll
                for (int fm = 0; fm < 2; fm++) {
                    const int i_g = hc * 4 + wm * 2 + fm;
                    const float blo = bias[(size_t)(j * 64 + i_g) * 16 + gid];
                    const float bhi = bias[(size_t)(j * 64 + i_g) * 16 + gid + 8];
#pragma unroll
                    for (int fn = 0; fn < 4; fn++) {
                        c[fm][fn][0] += blo;
                        c[fm][fn][1] += blo;
                        c[fm][fn][2] += bhi;
                        c[fm][fn][3] += bhi;
                    }
                }
            }

            // (no barrier needed here: prev apply reads of Us finished before
            //  the step-start __syncthreads; each warp's Us slice is disjoint)

            // ---- C-frags -> Us[b][m], stride 68 ----
#pragma unroll
            for (int fm = 0; fm < 2; fm++)
#pragma unroll
                for (int fn = 0; fn < 4; fn++) {
                    const int m = (wm * 2 + fm) * 16 + gid;
                    const int n = (wn * 4 + fn) * 8 + 2 * tig;
                    Us[n * USTRIDE + m]           = c[fm][fn][0];
                    Us[(n + 1) * USTRIDE + m]     = c[fm][fn][1];
                    Us[n * USTRIDE + m + 8]       = c[fm][fn][2];
                    Us[(n + 1) * USTRIDE + m + 8] = c[fm][fn][3];
                }
            __syncthreads();

            // ---- apply (paired lanes: U reads term1 / F reads term2 broadcast) ----
            const float* ub = Us + b_l * USTRIDE;
            const float* fb = Fs + b_l * USTRIDE;
            if (term == 0) {
                // out[p][r] += sum_q F[p][q] * U[(il,q,r)]
#pragma unroll
                for (int il = 0; il < 4; il++) {
                    ulonglong2 uq[4];
#pragma unroll
                    for (int q = 0; q < 4; q++)
                        uq[q] = *(const ulonglong2*)(ub + il * 16 + q * 4);
#pragma unroll
                    for (int pp = 0; pp < 2; pp++) {
                        const float4 f = *(const float4*)(fb + il * 16 + (p0 + pp) * 4);
                        const float fv[4] = {f.x, f.y, f.z, f.w};
#pragma unroll
                        for (int q = 0; q < 4; q++) {
                            const ull fs = splat2(fv[q]);
                            o01[pp] = fma2(fs, uq[q].x, o01[pp]);
                            o23[pp] = fma2(fs, uq[q].y, o23[pp]);
                        }
                    }
                }
            } else {
                // out[p][r] += sum_q Ub[(il,p,q)] * F[q][r]
#pragma unroll
                for (int il = 0; il < 4; il++) {
                    ull f01[4], f23[4];
#pragma unroll
                    for (int q = 0; q < 4; q++) {
                        const float4 fq = *(const float4*)(fb + il * 16 + q * 4);
                        f01[q] = pack2(fq.x, fq.y);
                        f23[q] = pack2(fq.z, fq.w);
                    }
#pragma unroll
                    for (int pp = 0; pp < 2; pp++) {
                        const float4 u = *(const float4*)(ub + il * 16 + (p0 + pp) * 4);
                        const float uv[4] = {u.x, u.y, u.z, u.w};
#pragma unroll
                        for (int q = 0; q < 4; q++) {
                            const ull gs = splat2(uv[q]);
                            o01[pp] = fma2(gs, f01[q], o01[pp]);
                            o23[pp] = fma2(gs, f23[q], o23[pp]);
                        }
                    }
                }
            }
        }
    }

    // ---- final write: out[b, j, p, 0..3] for p = p0, p0+1 ----
#pragma unroll
    for (int pp = 0; pp < 2; pp++) {
        float4 o;
        unpack2(o01[pp], o.x, o.y);
        unpack2(o23[pp], o.z, o.w);
        ((float4*)out)[(size_t)((bt * 128 + b_l) * 64 + j) * 4 + (p0 + pp)] = o;
    }
}

// ============================================================================
// Launch
// ============================================================================
extern "C" void kernel_launch(void* const* d_in, const int* in_sizes, int n_in,
                              void* d_out, int out_size) {
    (void)in_sizes; (void)n_in; (void)out_size;
    const float* F   = (const float*)d_in[0];
    const float* th  = (const float*)d_in[1];
    const float* Wb  = (const float*)d_in[2];
    const float* Wc  = (const float*)d_in[3];
    const float* Ws  = (const float*)d_in[4];
    const float* Wbb = (const float*)d_in[5];
    const float* Wbc = (const float*)d_in[6];
    const float* Wbs = (const float*)d_in[7];

    cudaFuncSetAttribute(main_kernel, cudaFuncAttributeMaxDynamicSharedMemorySize, SMEM_DYN);

    prep_w<<<2 * 64 * HC, 256>>>(Wc, Ws, Wbc, Wbs);
    prep_v<<<32, 256>>>(th);
    main_kernel<<<dim3(4, 64), 256, SMEM_DYN>>>(F, Wb, Wbb, (float*)d_out);
}

// round 7
// speedup vs baseline: 2.9051x; 1.0466x over previous
#include <cuda_runtime.h>
#include <cstdint>

// ============================================================================
// Problem constants
// ============================================================================
namespace {
constexpr int CI = 64, CO = 64, CJ = 16, B_ = 512;
constexpr int HC   = 16;          // i-chunks of 4
constexpr int KT   = 4;           // k-tiles of 8 (K = 32; bias via epilogue)
constexpr int USTRIDE = 68;       // floats per b-row in Us/Fs (64 + 4 pad)
constexpr int SMEM_HALF = 128 * USTRIDE;            // 8704 floats
constexpr int A_STEP_U4 = KT * 4 * 32;              // 512 uint4 per step
constexpr int A_STEP_FL = A_STEP_U4 * 4;            // 2048 floats
constexpr int SMEM_FLOATS = 2 * SMEM_HALF + 2 * A_STEP_FL;   // 21504
constexpr int SMEM_DYN  = SMEM_FLOATS * 4;                   // 86016 bytes
using ull = unsigned long long;
}

// A fragments: [term][j][hc][kt(4)][mt(4)][lane(32)][4]  (tf32 bits)
__device__ uint32_t g_wa[2 * 64 * HC * KT * 4 * 32 * 4];   // 16.8MB
// B fragments: [bt(4)][nt(16)][kt(4)][lane(32)] x uint2  (tf32 bits)
__device__ uint32_t g_vb[4 * 16 * KT * 32 * 2];

// ============================================================================
// helpers
// ============================================================================
__device__ __forceinline__ uint32_t f2tf32(float f) {
    uint32_t r;
    asm("cvt.rna.tf32.f32 %0, %1;" : "=r"(r) : "f"(f));
    return r;
}
__device__ __forceinline__ ull fma2(ull a, ull b, ull c) {
    ull d;
    asm("fma.rn.f32x2 %0, %1, %2, %3;" : "=l"(d) : "l"(a), "l"(b), "l"(c));
    return d;
}
__device__ __forceinline__ ull splat2(float x) {
    ull r;
    asm("mov.b64 %0, {%1, %1};" : "=l"(r) : "f"(x));
    return r;
}
__device__ __forceinline__ ull pack2(float lo, float hi) {
    ull r;
    asm("mov.b64 %0, {%1, %2};" : "=l"(r) : "f"(lo), "f"(hi));
    return r;
}
__device__ __forceinline__ void unpack2(ull v, float& lo, float& hi) {
    asm("mov.b64 {%0, %1}, %2;" : "=f"(lo), "=f"(hi) : "l"(v));
}
__device__ __forceinline__ void mma_tf32(float c[4], uint32_t a0, uint32_t a1,
                                         uint32_t a2, uint32_t a3,
                                         uint32_t b0, uint32_t b1) {
    asm volatile(
        "mma.sync.aligned.m16n8k8.row.col.f32.tf32.tf32.f32 "
        "{%0,%1,%2,%3}, {%4,%5,%6,%7}, {%8,%9}, {%0,%1,%2,%3};"
        : "+f"(c[0]), "+f"(c[1]), "+f"(c[2]), "+f"(c[3])
        : "r"(a0), "r"(a1), "r"(a2), "r"(a3), "r"(b0), "r"(b1));
}
__device__ __forceinline__ void cpa16(uint32_t s, const void* g) {
    asm volatile("cp.async.cg.shared.global [%0], [%1], 16;" :: "r"(s), "l"(g));
}
__device__ __forceinline__ void cp_commit() { asm volatile("cp.async.commit_group;"); }
template <int N>
__device__ __forceinline__ void cp_wait() { asm volatile("cp.async.wait_group %0;" :: "n"(N)); }

// ============================================================================
// Prep 1: weight A-fragments.  K=32: k 0..15 = cos(c=k), 16..31 = sin
// ============================================================================
__global__ void __launch_bounds__(256) prep_w(
    const float* __restrict__ Wc,  const float* __restrict__ Ws,
    const float* __restrict__ Wbc, const float* __restrict__ Wbs)
{
    __shared__ float sC[4][256], sS[4][256];
    const int bid  = blockIdx.x;
    const int term = bid >> 10;
    const int j    = (bid >> 4) & 63;
    const int hc   = bid & 15;
    const int i0   = hc * 4;
    const int t    = threadIdx.x;

    const float* pC = term ? Wbc : Wc;
    const float* pS = term ? Wbs : Ws;

    ((float4*)sC)[t] = ((const float4*)(pC + (size_t)(j * 64 + i0) * 256))[t];
    ((float4*)sS)[t] = ((const float4*)(pS + (size_t)(j * 64 + i0) * 256))[t];
    __syncthreads();

    auto wval = [&](int i, int rr, int k) -> float {
        return (k < 16) ? sC[i][k * 16 + rr] : sS[i][(k - 16) * 16 + rr];
    };

    for (int e = t; e < KT * 4 * 32; e += 256) {
        const int lane = e & 31, mt = (e >> 5) & 3, kt = e >> 7;
        const int rr = lane >> 2, k = kt * 8 + (lane & 3);
        uint4 o;
        o.x = f2tf32(wval(mt, rr,     k));
        o.y = f2tf32(wval(mt, rr + 8, k));
        o.z = f2tf32(wval(mt, rr,     k + 4));
        o.w = f2tf32(wval(mt, rr + 8, k + 4));
        ((uint4*)g_wa)[((bid * KT + kt) * 4 + mt) * 32 + lane] = o;
    }
}

// ============================================================================
// Prep 2: trig B-fragments
// ============================================================================
__global__ void __launch_bounds__(256) prep_v(const float* __restrict__ theta) {
    const int t = blockIdx.x * 256 + threadIdx.x;   // 8192 total
    const int lane = t & 31;
    const int kt   = (t >> 5) & 3;
    const int nt   = (t >> 7) & 15;
    const int bt   = t >> 11;
    const int b    = bt * 128 + nt * 8 + (lane >> 2);
    const int k0   = kt * 8 + (lane & 3);

    auto vval = [&](int k) -> float {
        return (k < 16) ? cosf(theta[b * CJ + k]) : sinf(theta[b * CJ + (k - 16)]);
    };
    uint2 o;
    o.x = f2tf32(vval(k0));
    o.y = f2tf32(vval(k0 + 4));
    ((uint2*)g_vb)[((bt * 16 + nt) * KT + kt) * 32 + lane] = o;
}

// ============================================================================
// Main kernel — cross-step pipeline: mma(s) overlapped with apply(s-1)
// ============================================================================
__global__ void __launch_bounds__(256, 2) main_kernel(
    const float* __restrict__ F,     // (B, CI, 4, 4)
    const float* __restrict__ Wb,    // bias term1 (flat rr = q*4+r)
    const float* __restrict__ Wbb,   // bias term2 (flat rr = p*4+q)
    float* __restrict__ out)         // (B, CO, 4, 4)
{
    extern __shared__ float sm[];
    float* Us = sm;
    float* Fs = sm + SMEM_HALF;
    float* A0 = sm + 2 * SMEM_HALF;
    float* A1 = A0 + A_STEP_FL;

    const int tid  = threadIdx.x;
    const int wid  = tid >> 5;
    const int lane = tid & 31;
    const int bt   = blockIdx.x;
    const int j    = blockIdx.y;
    const int wm   = wid & 1;
    const int wn   = wid >> 1;
    const int gid  = lane >> 2;
    const int tig  = lane & 3;
    const int b_l  = tid >> 1;       // paired lanes share b (LDS broadcast)
    const int p0   = (tid & 1) * 2;

    ull o01[2] = {0ull, 0ull}, o23[2] = {0ull, 0ull};

    // Vb fragments in registers (invariant over steps)
    uint2 vb[KT][4];
    {
        const uint2* Vb = (const uint2*)g_vb;
#pragma unroll
        for (int kt = 0; kt < KT; kt++)
#pragma unroll
            for (int fn = 0; fn < 4; fn++)
                vb[kt][fn] = Vb[((bt * 16 + wn * 4 + fn) * KT + kt) * 32 + lane];
    }

    auto prefetch_A = [&](int s, float* dst) {
        const int term = s & 1, hc = s >> 1;
        const uint4* src = ((const uint4*)g_wa) +
                           (size_t)((term * 1024 + j * 16 + hc) * KT) * 128;
        const uint32_t sa = (uint32_t)__cvta_generic_to_shared(dst);
#pragma unroll
        for (int e = tid; e < A_STEP_U4; e += 256)
            cpa16(sa + (uint32_t)e * 16u, src + e);
    };

    // stage Fs(hc) via cp.async (own commit group)
    auto stage_F = [&](int hc) {
        const uint32_t sa = (uint32_t)__cvta_generic_to_shared(Fs);
#pragma unroll
        for (int pass = 0; pass < 8; pass++) {
            const int v  = pass * 256 + tid;
            const int bb = v >> 4;
            const int x  = v & 15;
            cpa16(sa + (uint32_t)(bb * USTRIDE + x * 4) * 4u,
                  ((const float4*)F) + (size_t)(bt * 128 + bb) * 256 +
                  (hc * 4 + (x >> 2)) * 4 + (x & 3));
        }
        cp_commit();
    };

    // apply(previous step): pterm = term of step s-1
    auto apply_prev = [&](int pterm) {
        const float* ub = Us + b_l * USTRIDE;
        const float* fb = Fs + b_l * USTRIDE;
        if (pterm == 0) {
            // out[p][r] += sum_q F[p][q] * U[(il,q,r)]
#pragma unroll
            for (int il = 0; il < 4; il++) {
                ulonglong2 uq[4];
#pragma unroll
                for (int q = 0; q < 4; q++)
                    uq[q] = *(const ulonglong2*)(ub + il * 16 + q * 4);
#pragma unroll
                for (int pp = 0; pp < 2; pp++) {
                    const float4 f = *(const float4*)(fb + il * 16 + (p0 + pp) * 4);
                    const float fv[4] = {f.x, f.y, f.z, f.w};
#pragma unroll
                    for (int q = 0; q < 4; q++) {
                        const ull fs = splat2(fv[q]);
                        o01[pp] = fma2(fs, uq[q].x, o01[pp]);
                        o23[pp] = fma2(fs, uq[q].y, o23[pp]);
                    }
                }
            }
        } else {
            // out[p][r] += sum_q Ub[(il,p,q)] * F[q][r]
#pragma unroll
            for (int il = 0; il < 4; il++) {
                ull f01[4], f23[4];
#pragma unroll
                for (int q = 0; q < 4; q++) {
                    const float4 fq = *(const float4*)(fb + il * 16 + q * 4);
                    f01[q] = pack2(fq.x, fq.y);
                    f23[q] = pack2(fq.z, fq.w);
                }
#pragma unroll
                for (int pp = 0; pp < 2; pp++) {
                    const float4 u = *(const float4*)(ub + il * 16 + (p0 + pp) * 4);
                    const float uv[4] = {u.x, u.y, u.z, u.w};
#pragma unroll
                    for (int q = 0; q < 4; q++) {
                        const ull gs = splat2(uv[q]);
                        o01[pp] = fma2(gs, f01[q], o01[pp]);
                        o23[pp] = fma2(gs, f23[q], o23[pp]);
                    }
                }
            }
        }
    };

    prefetch_A(0, A0);
    cp_commit();

    for (int s = 0; s < 2 * HC; s++) {
        const int term = s & 1;
        const int hc   = s >> 1;

        if (s + 1 < 2 * HC) {
            prefetch_A(s + 1, (s & 1) ? A0 : A1);
            cp_commit();
            cp_wait<1>();     // drains A(s) and (if present) Fs group
        } else {
            cp_wait<0>();
        }
        __syncthreads();      // A(s), Us(s-1), Fs visible

        // ==== interleave region: mma(s) + apply(s-1), disjoint pipes ====
        float c[2][4][4];
#pragma unroll
        for (int fm = 0; fm < 2; fm++)
#pragma unroll
            for (int fn = 0; fn < 4; fn++)
#pragma unroll
                for (int e = 0; e < 4; e++) c[fm][fn][e] = 0.0f;

        const uint4* As = (const uint4*)((s & 1) ? A1 : A0);
#pragma unroll
        for (int kt = 0; kt < KT; kt++) {
            uint4 a[2];
            a[0] = As[(kt * 4 + wm * 2 + 0) * 32 + lane];
            a[1] = As[(kt * 4 + wm * 2 + 1) * 32 + lane];
#pragma unroll
            for (int fm = 0; fm < 2; fm++)
#pragma unroll
                for (int fn = 0; fn < 4; fn++)
                    mma_tf32(c[fm][fn], a[fm].x, a[fm].y, a[fm].z, a[fm].w,
                             vb[kt][fn].x, vb[kt][fn].y);
        }

        if (s > 0) apply_prev(1 - term);   // overlaps with HMMA above

        // bias add in fp32
        {
            const float* bias = term ? Wbb : Wb;
#pragma unroll
            for (int fm = 0; fm < 2; fm++) {
                const int i_g = hc * 4 + wm * 2 + fm;
                const float blo = bias[(size_t)(j * 64 + i_g) * 16 + gid];
                const float bhi = bias[(size_t)(j * 64 + i_g) * 16 + gid + 8];
#pragma unroll
                for (int fn = 0; fn < 4; fn++) {
                    c[fm][fn][0] += blo;
                    c[fm][fn][1] += blo;
                    c[fm][fn][2] += bhi;
                    c[fm][fn][3] += bhi;
                }
            }
        }

        __syncthreads();      // apply(s-1) reads of Us/Fs complete CTA-wide

        // ==== post region: store Us(s); stage Fs(hc) on term0 steps ====
#pragma unroll
        for (int fm = 0; fm < 2; fm++)
#pragma unroll
            for (int fn = 0; fn < 4; fn++) {
                const int m = (wm * 2 + fm) * 16 + gid;
                const int n = (wn * 4 + fn) * 8 + 2 * tig;
                Us[n * USTRIDE + m]           = c[fm][fn][0];
                Us[(n + 1) * USTRIDE + m]     = c[fm][fn][1];
                Us[n * USTRIDE + m + 8]       = c[fm][fn][2];
                Us[(n + 1) * USTRIDE + m + 8] = c[fm][fn][3];
            }

        if (term == 0) stage_F(hc);   // Fs(hc-1) dead; own commit group
    }

    // ==== tail: apply(last step = term1) ====
    cp_wait<0>();
    __syncthreads();
    apply_prev(1);

    // final write
#pragma unroll
    for (int pp = 0; pp < 2; pp++) {
        float4 o;
        unpack2(o01[pp], o.x, o.y);
        unpack2(o23[pp], o.z, o.w);
        ((float4*)out)[(size_t)((bt * 128 + b_l) * 64 + j) * 4 + (p0 + pp)] = o;
    }
}

// ============================================================================
// Launch
// ============================================================================
extern "C" void kernel_launch(void* const* d_in, const int* in_sizes, int n_in,
                              void* d_out, int out_size) {
    (void)in_sizes; (void)n_in; (void)out_size;
    const float* F   = (const float*)d_in[0];
    const float* th  = (const float*)d_in[1];
    const float* Wb  = (const float*)d_in[2];
    const float* Wc  = (const float*)d_in[3];
    const float* Ws  = (const float*)d_in[4];
    const float* Wbb = (const float*)d_in[5];
    const float* Wbc = (const float*)d_in[6];
    const float* Wbs = (const float*)d_in[7];

    cudaFuncSetAttribute(main_kernel, cudaFuncAttributeMaxDynamicSharedMemorySize, SMEM_DYN);

    prep_w<<<2 * 64 * HC, 256>>>(Wc, Ws, Wbc, Wbs);
    prep_v<<<32, 256>>>(th);
    main_kernel<<<dim3(4, 64), 256, SMEM_DYN>>>(F, Wb, Wbb, (float*)d_out);
}